// round 16
// baseline (speedup 1.0000x reference)
#include <cuda_runtime.h>
#include <cuda_fp16.h>
#include <cstdint>

// Problem constants
#define B_   1024
#define P_   24
#define H_   2048
#define K1_  4096   // H*R
#define N1_  2048   // H
#define K2_  2048
#define N2_  1024   // H/2
#define OUTP 4

// Scratch (allocation-free rule: __device__ globals)
__device__ __half g_xh [(size_t)B_ * P_ * H_];    // x   -> fp16
__device__ __half g_w1h[(size_t)P_ * K1_ * N1_];  // W1  -> fp16
__device__ __half g_w2h[(size_t)P_ * K2_ * N2_];  // W2  -> fp16
__device__ __half g_h1h[(size_t)P_ * B_ * N1_];   // layer1 out fp16
__device__ float  g_part[(size_t)P_ * B_ * 8 * OUTP]; // L3 partials [P][B][8][4]
__device__ unsigned g_qctr;                       // work-queue counter
__device__ unsigned g_cnt_x;                      // x cvt completions
__device__ unsigned g_cnt_w1[P_];                 // W1 cvt completions per p
__device__ unsigned g_cnt_g1[P_];                 // GEMM1 tile completions per p

// ---------------------------------------------------------------------------
// helpers
// ---------------------------------------------------------------------------
__device__ __forceinline__ void mma_f16_f32(float* c, const uint32_t* a, const uint32_t* b) {
    asm volatile(
        "mma.sync.aligned.m16n8k16.row.col.f32.f16.f16.f32 "
        "{%0,%1,%2,%3}, {%4,%5,%6,%7}, {%8,%9}, {%0,%1,%2,%3};"
        : "+f"(c[0]), "+f"(c[1]), "+f"(c[2]), "+f"(c[3])
        : "r"(a[0]), "r"(a[1]), "r"(a[2]), "r"(a[3]), "r"(b[0]), "r"(b[1]));
}

__device__ __forceinline__ void ldsm4(uint32_t addr, uint32_t* r) {
    asm volatile("ldmatrix.sync.aligned.m8n8.x4.shared.b16 {%0,%1,%2,%3}, [%4];"
                 : "=r"(r[0]), "=r"(r[1]), "=r"(r[2]), "=r"(r[3]) : "r"(addr));
}
__device__ __forceinline__ void ldsm4t(uint32_t addr, uint32_t* r) {
    asm volatile("ldmatrix.sync.aligned.m8n8.x4.trans.shared.b16 {%0,%1,%2,%3}, [%4];"
                 : "=r"(r[0]), "=r"(r[1]), "=r"(r[2]), "=r"(r[3]) : "r"(addr));
}

__device__ __forceinline__ void cp_async16(uint32_t smem_addr, const void* gptr, int src_size) {
    asm volatile("cp.async.cg.shared.global [%0], [%1], 16, %2;"
                 :: "r"(smem_addr), "l"(gptr), "r"(src_size));
}
__device__ __forceinline__ void cp_commit() {
    asm volatile("cp.async.commit_group;" ::: "memory");
}
template <int N>
__device__ __forceinline__ void cp_wait() {
    asm volatile("cp.async.wait_group %0;" :: "n"(N) : "memory");
}

__device__ __forceinline__ float gelu_exact(float v) {
    return 0.5f * v * (1.0f + erff(v * 0.7071067811865476f));
}

__device__ __forceinline__ unsigned ld_acq(const unsigned* p) {
    unsigned v;
    asm volatile("ld.acquire.gpu.u32 %0, [%1];" : "=r"(v) : "l"(p));
    return v;
}

// ---------------------------------------------------------------------------
// reset: zero all counters (first node of every replay)
// ---------------------------------------------------------------------------
__global__ void reset_kernel() {
    g_qctr = 0; g_cnt_x = 0;
    for (int i = 0; i < P_; i++) { g_cnt_w1[i] = 0; g_cnt_g1[i] = 0; }
}

// ---------------------------------------------------------------------------
// Work queue with dependency LOOKAHEAD (consumers claimed >= 2 segments after
// their producers finish claiming -> spins are rare):
//   Phase A [0,1024):      768 x chunks, then W1[0](128), W1[1](128)
//   Phase B [1024,8704):   24 segments of 320:
//        seg p: [0,128)=G1[p] tiles, [128,256)=W1[p+2] chunks (p<22),
//               [256,320)=G2[p-2] tiles (p>=2); out-of-range slots = no-op
//   Tail   [8704,8832):    G2[22](64), G2[23](64)
// Deadlock-free: claims monotonic; spinners never block claimers; every item
// ahead in the queue completes unconditionally.  Deterministic outputs.
// ---------------------------------------------------------------------------
#define XITEMS   768
#define XF4      16384
#define W1F4     16384
#define APHASE   1024
#define SEGSZ    320
#define BPHASE   (APHASE + P_ * SEGSZ)   // 8704
#define NITEMS   (BPHASE + 128)          // 8832

#define OPX  0
#define OPW1 1
#define OPG1 2
#define OPG2 3

#define BM 128
#define BN 128
#define BK 64
#define ASTRH 72
#define BSTRH 136
#define ASZB (BM * ASTRH * 2)          // 18432 B
#define BSZB (BK * BSTRH * 2)          // 17408 B
#define STGB (ASZB + BSZB)             // 35840 B / stage
#define NSTG 3
#define PIPE_BYTES (NSTG * STGB)       // 107520
#define W3_OFF   PIPE_BYTES
#define SRED_OFF (PIPE_BYTES + 2048)
#define SMEM_ALL (PIPE_BYTES + 2048 + 4096)   // 113664

__global__ void __launch_bounds__(128, 2)
mega_kernel(const float* __restrict__ x,  const float* __restrict__ W1,
            const float* __restrict__ b1, const float* __restrict__ W2,
            const float* __restrict__ b2, const float* __restrict__ W3,
            __half* __restrict__ xh, __half* __restrict__ w1h,
            __half* __restrict__ w2h, __half* __restrict__ h1h,
            float* __restrict__ part) {
    extern __shared__ __half smem[];
    char* smem_c = (char*)smem;
    const uint32_t smem_u = (uint32_t)__cvta_generic_to_shared(smem);
    __shared__ int s_tile;

    const int tid  = threadIdx.x;
    const int wid  = tid >> 5;
    const int lane = tid & 31;
    const int warpM = wid >> 1;
    const int warpN = wid & 1;
    const int g  = lane >> 2;
    const int cc = lane & 3;

    const int l7 = lane & 7;
    const int lb = (lane >> 3) & 1;
    const int lk = lane >> 4;
    const uint32_t aoff = ((warpM * 64 + lb * 8 + l7) * ASTRH + lk * 8) * 2;
    const uint32_t boff = ASZB + ((lb * 8 + l7) * BSTRH + warpN * 64 + lk * 8) * 2;

    while (true) {
        if (tid == 0) s_tile = (int)atomicAdd(&g_qctr, 1u);
        __syncthreads();
        const int item = s_tile;
        if (item >= NITEMS) break;

        // -------- decode --------
        int op, p = 0, s = 0;
        if (item < XITEMS) { op = OPX; s = item; }
        else if (item < APHASE) { op = OPW1; p = (item - XITEMS) >> 7; s = (item - XITEMS) & 127; }
        else if (item < BPHASE) {
            int r = item - APHASE;
            int sp = r / SEGSZ;
            int ss = r % SEGSZ;
            if (ss < 128)       { op = OPG1; p = sp; s = ss; }
            else if (ss < 256)  { op = OPW1; p = sp + 2; s = ss - 128;
                                  if (p >= P_) continue; }
            else                { op = OPG2; p = sp - 2; s = ss - 256;
                                  if (p < 0) continue; }
        } else {
            int r = item - BPHASE;
            op = OPG2; p = 22 + (r >> 6); s = r & 63;
        }

        // ------------------------------------------------------------------
        // x convert chunk
        // ------------------------------------------------------------------
        if (op == OPX) {
            size_t base = (size_t)s * XF4 + tid;
            const float4* src = (const float4*)x;
            __half2* dst = (__half2*)xh;
#pragma unroll 8
            for (int i = 0; i < XF4 / 128; i++) {
                size_t idx = base + (size_t)i * 128;
                float4 v = __ldg(&src[idx]);
                dst[2 * idx]     = __floats2half2_rn(v.x, v.y);
                dst[2 * idx + 1] = __floats2half2_rn(v.z, v.w);
            }
            __threadfence(); __syncthreads();
            if (tid == 0) atomicAdd(&g_cnt_x, 1u);
            continue;
        }

        // ------------------------------------------------------------------
        // W1[p] convert chunk
        // ------------------------------------------------------------------
        if (op == OPW1) {
            size_t base = (size_t)p * (128 * (size_t)W1F4) + (size_t)s * W1F4 + tid;
            const float4* src = (const float4*)W1;
            __half2* dst = (__half2*)w1h;
#pragma unroll 8
            for (int i = 0; i < W1F4 / 128; i++) {
                size_t idx = base + (size_t)i * 128;
                float4 v = __ldg(&src[idx]);
                dst[2 * idx]     = __floats2half2_rn(v.x, v.y);
                dst[2 * idx + 1] = __floats2half2_rn(v.z, v.w);
            }
            __threadfence(); __syncthreads();
            if (tid == 0) atomicAdd(&g_cnt_w1[p], 1u);
            continue;
        }

        // ------------------------------------------------------------------
        // GEMM1 tile (p, bm, bn) + W2 cvt side job
        // ------------------------------------------------------------------
        if (op == OPG1) {
            const int tl = s;
            const int bn = tl & 15, bm = tl >> 4;
            if (tid == 0) {
                while (ld_acq(&g_cnt_x) < XITEMS) __nanosleep(64);
                while (ld_acq(&g_cnt_w1[p]) < 128) __nanosleep(64);
            }
            __syncthreads();

            float acc[4][8][4];
#pragma unroll
            for (int mf = 0; mf < 4; mf++)
#pragma unroll
                for (int nf = 0; nf < 8; nf++)
#pragma unroll
                    for (int i = 0; i < 4; i++) acc[mf][nf][i] = 0.f;

            const __half* Wp = w1h + (size_t)p * K1_ * N1_ + (size_t)bn * BN;

            auto load_A = [&](int kt, int buf) {
                uint32_t sbase = smem_u + buf * STGB;
#pragma unroll
                for (int i = 0; i < 8; i++) {
                    int c  = tid + i * 128;
                    int m  = c >> 3;
                    int kl = (c & 7) * 8;
                    int kg = kt * BK + kl;
                    int half_ = (kg >= H_) ? 1 : 0;
                    int pp    = p + half_;
                    int kk    = kg - half_ * H_;
                    int sz = 16;
                    if (pp >= P_) { pp = P_ - 1; sz = 0; }
                    const __half* ga = xh + ((size_t)(bm * BM + m) * P_ + pp) * H_ + kk;
                    cp_async16(sbase + (m * ASTRH + kl) * 2, ga, sz);
                }
            };
            auto load_B = [&](int kt, int buf) {
                uint32_t sbase = smem_u + buf * STGB;
#pragma unroll
                for (int i = 0; i < 8; i++) {
                    int c  = tid + i * 128;
                    int kb = c >> 4;
                    int nb = (c & 15) * 8;
                    const __half* gb = Wp + (size_t)(kt * BK + kb) * N1_ + nb;
                    cp_async16(sbase + ASZB + (kb * BSTRH + nb) * 2, gb, 16);
                }
            };

            uint32_t a[2][4][4], b[2][4][4];
            auto prefetch = [&](uint32_t sbase, int ks, int buf) {
                const uint32_t akk = sbase + aoff + ks * 32;
                const uint32_t bkk = sbase + boff + ks * (16 * BSTRH * 2);
#pragma unroll
                for (int f = 0; f < 4; f++) ldsm4(akk + f * (16 * ASTRH * 2), a[buf][f]);
#pragma unroll
                for (int nf = 0; nf < 4; nf++) ldsm4t(bkk + nf * 32, b[buf][nf]);
            };
            auto mma_block = [&](int buf) {
#pragma unroll
                for (int mf = 0; mf < 4; mf++)
#pragma unroll
                    for (int nf = 0; nf < 4; nf++) {
                        mma_f16_f32(acc[mf][2 * nf],     a[buf][mf], &b[buf][nf][0]);
                        mma_f16_f32(acc[mf][2 * nf + 1], a[buf][mf], &b[buf][nf][2]);
                    }
            };

            const int NKT = (p == P_ - 1) ? (H_ / BK) : (K1_ / BK);

            load_A(0, 0); load_B(0, 0); cp_commit();
            load_A(1, 1); load_B(1, 1); cp_commit();
            cp_wait<1>(); __syncthreads();
            prefetch(smem_u, 0, 0);

            for (int kt = 0; kt < NKT; ++kt) {
                const uint32_t sbase = smem_u + (kt % NSTG) * STGB;
                const bool more = (kt + 2 < NKT);
                const int  nbuf = (kt + 2) % NSTG;

                prefetch(sbase, 1, 1);
                if (more) load_A(kt + 2, nbuf);
                mma_block(0);
                prefetch(sbase, 2, 0);
                if (more) load_B(kt + 2, nbuf);
                mma_block(1);
                prefetch(sbase, 3, 1);
                mma_block(0);

                if (more) { cp_commit(); cp_wait<1>(); }
                else      { cp_wait<0>(); }
                __syncthreads();
                if (kt + 1 < NKT) prefetch(smem_u + ((kt + 1) % NSTG) * STGB, 0, 0);
                mma_block(1);
            }

            const float* brow = b1 + (size_t)p * N1_;
#pragma unroll
            for (int mf = 0; mf < 4; mf++) {
                int row0 = bm * BM + warpM * 64 + mf * 16 + g;
                size_t base0 = ((size_t)p * B_ + row0) * (size_t)N1_;
                size_t base8 = base0 + (size_t)8 * N1_;
#pragma unroll
                for (int nf = 0; nf < 8; nf++) {
                    int n = bn * BN + warpN * 64 + nf * 8 + cc * 2;
                    float bv0 = __ldg(brow + n);
                    float bv1 = __ldg(brow + n + 1);
                    float v0 = gelu_exact(acc[mf][nf][0] + bv0);
                    float v1 = gelu_exact(acc[mf][nf][1] + bv1);
                    float v2 = gelu_exact(acc[mf][nf][2] + bv0);
                    float v3 = gelu_exact(acc[mf][nf][3] + bv1);
                    *(__half2*)(h1h + base0 + n) = __floats2half2_rn(v0, v1);
                    *(__half2*)(h1h + base8 + n) = __floats2half2_rn(v2, v3);
                }
            }
            // Side job: convert W2 slice (tile id p*128+tl covers all of W2)
            {
                size_t base = ((size_t)p * 128 + tl) * 4096 + tid;
                const float4* w2src = (const float4*)W2;
                __half2* w2dst = (__half2*)w2h;
#pragma unroll 4
                for (int i = 0; i < 32; i++) {
                    size_t idx = base + (size_t)i * 128;
                    float4 v = __ldg(&w2src[idx]);
                    w2dst[2 * idx]     = __floats2half2_rn(v.x, v.y);
                    w2dst[2 * idx + 1] = __floats2half2_rn(v.z, v.w);
                }
            }
            __threadfence(); __syncthreads();
            if (tid == 0) atomicAdd(&g_cnt_g1[p], 1u);
            continue;
        }

        // ------------------------------------------------------------------
        // GEMM2 tile (p, bm, bn): fused L3 partials
        // ------------------------------------------------------------------
        {
            const int tl = s;
            const int bn = tl & 7, bm = tl >> 3;
            if (tid == 0) {
                while (ld_acq(&g_cnt_g1[p]) < 128) __nanosleep(64);
            }
            __syncthreads();

            {
                const float4* w3g = (const float4*)(W3 + ((size_t)p * N2_ + bn * BN) * OUTP);
                ((float4*)(smem_c + W3_OFF))[tid] = __ldg(&w3g[tid]);
            }

            float acc[4][8][4];
#pragma unroll
            for (int mf = 0; mf < 4; mf++)
#pragma unroll
                for (int nf = 0; nf < 8; nf++)
#pragma unroll
                    for (int i = 0; i < 4; i++) acc[mf][nf][i] = 0.f;

            const __half* Wp = w2h + (size_t)p * K2_ * N2_ + (size_t)bn * BN;

            auto load_A = [&](int kt, int buf) {
                uint32_t sbase = smem_u + buf * STGB;
#pragma unroll
                for (int i = 0; i < 8; i++) {
                    int c  = tid + i * 128;
                    int m  = c >> 3;
                    int kl = (c & 7) * 8;
                    const __half* ga = h1h + ((size_t)p * B_ + bm * BM + m) * (size_t)K2_
                                     + kt * BK + kl;
                    cp_async16(sbase + (m * ASTRH + kl) * 2, ga, 16);
                }
            };
            auto load_B = [&](int kt, int buf) {
                uint32_t sbase = smem_u + buf * STGB;
#pragma unroll
                for (int i = 0; i < 8; i++) {
                    int c  = tid + i * 128;
                    int kb = c >> 4;
                    int nb = (c & 15) * 8;
                    const __half* gb = Wp + (size_t)(kt * BK + kb) * N2_ + nb;
                    cp_async16(sbase + ASZB + (kb * BSTRH + nb) * 2, gb, 16);
                }
            };

            uint32_t a[2][4][4], b[2][4][4];
            auto prefetch = [&](uint32_t sbase, int ks, int buf) {
                const uint32_t akk = sbase + aoff + ks * 32;
                const uint32_t bkk = sbase + boff + ks * (16 * BSTRH * 2);
#pragma unroll
                for (int f = 0; f < 4; f++) ldsm4(akk + f * (16 * ASTRH * 2), a[buf][f]);
#pragma unroll
                for (int nf = 0; nf < 4; nf++) ldsm4t(bkk + nf * 32, b[buf][nf]);
            };
            auto mma_block = [&](int buf) {
#pragma unroll
                for (int mf = 0; mf < 4; mf++)
#pragma unroll
                    for (int nf = 0; nf < 4; nf++) {
                        mma_f16_f32(acc[mf][2 * nf],     a[buf][mf], &b[buf][nf][0]);
                        mma_f16_f32(acc[mf][2 * nf + 1], a[buf][mf], &b[buf][nf][2]);
                    }
            };

            const int NKT = K2_ / BK;

            load_A(0, 0); load_B(0, 0); cp_commit();
            load_A(1, 1); load_B(1, 1); cp_commit();
            cp_wait<1>(); __syncthreads();
            prefetch(smem_u, 0, 0);

            for (int kt = 0; kt < NKT; ++kt) {
                const uint32_t sbase = smem_u + (kt % NSTG) * STGB;
                const bool more = (kt + 2 < NKT);
                const int  nbuf = (kt + 2) % NSTG;

                prefetch(sbase, 1, 1);
                if (more) load_A(kt + 2, nbuf);
                mma_block(0);
                prefetch(sbase, 2, 0);
                if (more) load_B(kt + 2, nbuf);
                mma_block(1);
                prefetch(sbase, 3, 1);
                mma_block(0);

                if (more) { cp_commit(); cp_wait<1>(); }
                else      { cp_wait<0>(); }
                __syncthreads();
                if (kt + 1 < NKT) prefetch(smem_u + ((kt + 1) % NSTG) * STGB, 0, 0);
                mma_block(1);
            }

            const float* brow = b2 + (size_t)p * N2_;
            const float4* w3s = (const float4*)(smem_c + W3_OFF);
            float* sred = (float*)(smem_c + SRED_OFF);
            float pr[8][4];
#pragma unroll
            for (int rr = 0; rr < 8; rr++)
#pragma unroll
                for (int o = 0; o < 4; o++) pr[rr][o] = 0.f;

#pragma unroll
            for (int mf = 0; mf < 4; mf++) {
#pragma unroll
                for (int nf = 0; nf < 8; nf++) {
                    int ncol = warpN * 64 + nf * 8 + cc * 2;
                    float bv0 = __ldg(brow + bn * BN + ncol);
                    float bv1 = __ldg(brow + bn * BN + ncol + 1);
                    float v0 = gelu_exact(acc[mf][nf][0] + bv0);
                    float v1 = gelu_exact(acc[mf][nf][1] + bv1);
                    float v2 = gelu_exact(acc[mf][nf][2] + bv0);
                    float v3 = gelu_exact(acc[mf][nf][3] + bv1);
                    float4 wA = w3s[ncol];
                    float4 wB = w3s[ncol + 1];
                    int r0 = mf * 2, r1 = mf * 2 + 1;
                    pr[r0][0] += v0 * wA.x + v1 * wB.x;
                    pr[r0][1] += v0 * wA.y + v1 * wB.y;
                    pr[r0][2] += v0 * wA.z + v1 * wB.z;
                    pr[r0][3] += v0 * wA.w + v1 * wB.w;
                    pr[r1][0] += v2 * wA.x + v3 * wB.x;
                    pr[r1][1] += v2 * wA.y + v3 * wB.y;
                    pr[r1][2] += v2 * wA.z + v3 * wB.z;
                    pr[r1][3] += v2 * wA.w + v3 * wB.w;
                }
            }
#pragma unroll
            for (int rr = 0; rr < 8; rr++)
#pragma unroll
                for (int o = 0; o < 4; o++) {
                    float v = pr[rr][o];
                    v += __shfl_xor_sync(0xffffffffu, v, 1);
                    v += __shfl_xor_sync(0xffffffffu, v, 2);
                    pr[rr][o] = v;
                }
            if (cc == 0) {
#pragma unroll
                for (int rr = 0; rr < 8; rr++) {
                    int row = warpM * 64 + (rr >> 1) * 16 + (rr & 1) * 8 + g;
#pragma unroll
                    for (int o = 0; o < 4; o++)
                        sred[row * 8 + o * 2 + warpN] = pr[rr][o];
                }
            }
            __syncthreads();
            {
                int row = tid;
                size_t base = (((size_t)p * B_ + bm * BM + row) * 8 + bn) * OUTP;
#pragma unroll
                for (int o = 0; o < 4; o++)
                    part[base + o] = sred[row * 8 + o * 2] + sred[row * 8 + o * 2 + 1];
            }
            __syncthreads();
        }
    }
}

// ---------------------------------------------------------------------------
// L3 finisher: out[b, p*4+o] = relu(b3[p][o] + sum_{q=0..7} part[p][b][q][o])
// ---------------------------------------------------------------------------
__global__ void l3f_kernel(const float* __restrict__ part, const float* __restrict__ b3,
                           float* __restrict__ out) {
    int idx = blockIdx.x * blockDim.x + threadIdx.x;
    if (idx >= B_ * P_ * OUTP) return;
    int b = idx / (P_ * OUTP);
    int q = idx % (P_ * OUTP);
    int p = q / OUTP;
    int o = q % OUTP;
    const float* pp = part + (((size_t)p * B_ + b) * 8) * OUTP + o;
    float s = b3[p * OUTP + o];
#pragma unroll
    for (int j = 0; j < 8; j++) s += pp[j * OUTP];
    out[idx] = fmaxf(s, 0.f);
}

// ---------------------------------------------------------------------------
extern "C" void kernel_launch(void* const* d_in, const int* in_sizes, int n_in,
                              void* d_out, int out_size) {
    const float* x  = (const float*)d_in[0];
    const float* W1 = (const float*)d_in[1];
    const float* b1 = (const float*)d_in[2];
    const float* W2 = (const float*)d_in[3];
    const float* b2 = (const float*)d_in[4];
    const float* W3 = (const float*)d_in[5];
    const float* b3 = (const float*)d_in[6];
    float* out = (float*)d_out;

    __half *xh, *w1h, *w2h, *h1h;
    float *part;
    cudaGetSymbolAddress((void**)&xh,  g_xh);
    cudaGetSymbolAddress((void**)&w1h, g_w1h);
    cudaGetSymbolAddress((void**)&w2h, g_w2h);
    cudaGetSymbolAddress((void**)&h1h, g_h1h);
    cudaGetSymbolAddress((void**)&part, g_part);

    int smCount = 148;
    cudaDeviceGetAttribute(&smCount, cudaDevAttrMultiProcessorCount, 0);
    const int nCTA = 2 * smCount;

    cudaFuncSetAttribute((const void*)mega_kernel,
                         cudaFuncAttributeMaxDynamicSharedMemorySize, SMEM_ALL);

    // Reset counters (must be first each replay)
    reset_kernel<<<1, 1>>>();
    // Fused pipeline with dependency lookahead
    mega_kernel<<<nCTA, 128, SMEM_ALL>>>(x, W1, b1, W2, b2, W3,
                                         xh, w1h, w2h, h1h, part);
    // L3 finisher
    l3f_kernel<<<(B_ * P_ * OUTP + 255) / 256, 256>>>(part, b3, out);
}

// round 17
// speedup vs baseline: 1.4910x; 1.4910x over previous
#include <cuda_runtime.h>
#include <cuda_fp16.h>
#include <cstdint>

// Problem constants
#define B_   1024
#define P_   24
#define H_   2048
#define K1_  4096   // H*R
#define N1_  2048   // H
#define K2_  2048
#define N2_  1024   // H/2
#define OUTP 4

// Scratch (allocation-free rule: __device__ globals)
__device__ __half g_xh [(size_t)B_ * P_ * H_];    // x   -> fp16
__device__ __half g_w1h[(size_t)P_ * K1_ * N1_];  // W1  -> fp16
__device__ __half g_w2h[(size_t)P_ * K2_ * N2_];  // W2  -> fp16
__device__ __half g_h1h[(size_t)P_ * B_ * N1_];   // layer1 out fp16
__device__ float  g_part[(size_t)P_ * B_ * 8 * OUTP]; // L3 partials [P][B][8][4]
__device__ unsigned g_qctr;                       // work-queue counter
__device__ unsigned g_cnt_x;                      // x cvt completions
__device__ unsigned g_cnt_w1[P_];                 // W1 cvt completions per p
__device__ unsigned g_cnt_g1[P_];                 // GEMM1 tile completions per p

// ---------------------------------------------------------------------------
// helpers
// ---------------------------------------------------------------------------
__device__ __forceinline__ void mma_f16_f32(float* c, const uint32_t* a, const uint32_t* b) {
    asm volatile(
        "mma.sync.aligned.m16n8k16.row.col.f32.f16.f16.f32 "
        "{%0,%1,%2,%3}, {%4,%5,%6,%7}, {%8,%9}, {%0,%1,%2,%3};"
        : "+f"(c[0]), "+f"(c[1]), "+f"(c[2]), "+f"(c[3])
        : "r"(a[0]), "r"(a[1]), "r"(a[2]), "r"(a[3]), "r"(b[0]), "r"(b[1]));
}

__device__ __forceinline__ void ldsm4(uint32_t addr, uint32_t* r) {
    asm volatile("ldmatrix.sync.aligned.m8n8.x4.shared.b16 {%0,%1,%2,%3}, [%4];"
                 : "=r"(r[0]), "=r"(r[1]), "=r"(r[2]), "=r"(r[3]) : "r"(addr));
}
__device__ __forceinline__ void ldsm4t(uint32_t addr, uint32_t* r) {
    asm volatile("ldmatrix.sync.aligned.m8n8.x4.trans.shared.b16 {%0,%1,%2,%3}, [%4];"
                 : "=r"(r[0]), "=r"(r[1]), "=r"(r[2]), "=r"(r[3]) : "r"(addr));
}

__device__ __forceinline__ void cp_async16(uint32_t smem_addr, const void* gptr, int src_size) {
    asm volatile("cp.async.cg.shared.global [%0], [%1], 16, %2;"
                 :: "r"(smem_addr), "l"(gptr), "r"(src_size));
}
__device__ __forceinline__ void cp_commit() {
    asm volatile("cp.async.commit_group;" ::: "memory");
}
template <int N>
__device__ __forceinline__ void cp_wait() {
    asm volatile("cp.async.wait_group %0;" :: "n"(N) : "memory");
}

__device__ __forceinline__ float gelu_exact(float v) {
    return 0.5f * v * (1.0f + erff(v * 0.7071067811865476f));
}

__device__ __forceinline__ unsigned ld_acq(const unsigned* p) {
    unsigned v;
    asm volatile("ld.acquire.gpu.u32 %0, [%1];" : "=r"(v) : "l"(p));
    return v;
}

// ---------------------------------------------------------------------------
// reset: zero all counters (first node of every replay)
// ---------------------------------------------------------------------------
__global__ void reset_kernel() {
    g_qctr = 0; g_cnt_x = 0;
    for (int i = 0; i < P_; i++) { g_cnt_w1[i] = 0; g_cnt_g1[i] = 0; }
}

// ---------------------------------------------------------------------------
// Work queue with dependency LOOKAHEAD (consumers claimed >= 2 segments after
// their producers finish claiming -> spins are rare):
//   Phase A [0,1024):      768 x chunks, then W1[0](128), W1[1](128)
//   Phase B [1024,8704):   24 segments of 320:
//        seg p: [0,128)=G1[p] tiles, [128,256)=W1[p+2] chunks (p<22),
//               [256,320)=G2[p-2] tiles (p>=2); out-of-range slots = no-op
//   Tail   [8704,8832):    G2[22](64), G2[23](64)
// Deadlock-free: claims monotonic; spinners never block claimers; every item
// ahead in the queue completes unconditionally.  Deterministic outputs.
// ---------------------------------------------------------------------------
#define XITEMS   768
#define XF4      16384
#define W1F4     16384
#define APHASE   1024
#define SEGSZ    320
#define BPHASE   (APHASE + P_ * SEGSZ)   // 8704
#define NITEMS   (BPHASE + 128)          // 8832

#define OPX  0
#define OPW1 1
#define OPG1 2
#define OPG2 3

#define BM 128
#define BN 128
#define BK 64
#define ASTRH 72
#define BSTRH 136
#define ASZB (BM * ASTRH * 2)          // 18432 B
#define BSZB (BK * BSTRH * 2)          // 17408 B
#define STGB (ASZB + BSZB)             // 35840 B / stage
#define NSTG 3
#define PIPE_BYTES (NSTG * STGB)       // 107520
#define W3_OFF   PIPE_BYTES
#define SRED_OFF (PIPE_BYTES + 2048)
#define SMEM_ALL (PIPE_BYTES + 2048 + 4096)   // 113664

__global__ void __launch_bounds__(128, 2)
mega_kernel(const float* __restrict__ x,  const float* __restrict__ W1,
            const float* __restrict__ b1, const float* __restrict__ W2,
            const float* __restrict__ b2, const float* __restrict__ W3,
            __half* __restrict__ xh, __half* __restrict__ w1h,
            __half* __restrict__ w2h, __half* __restrict__ h1h,
            float* __restrict__ part) {
    extern __shared__ __half smem[];
    char* smem_c = (char*)smem;
    const uint32_t smem_u = (uint32_t)__cvta_generic_to_shared(smem);
    __shared__ int s_tile;

    const int tid  = threadIdx.x;
    const int wid  = tid >> 5;
    const int lane = tid & 31;
    const int warpM = wid >> 1;
    const int warpN = wid & 1;
    const int g  = lane >> 2;
    const int cc = lane & 3;

    const int l7 = lane & 7;
    const int lb = (lane >> 3) & 1;
    const int lk = lane >> 4;
    const uint32_t aoff = ((warpM * 64 + lb * 8 + l7) * ASTRH + lk * 8) * 2;
    const uint32_t boff = ASZB + ((lb * 8 + l7) * BSTRH + warpN * 64 + lk * 8) * 2;

    while (true) {
        if (tid == 0) s_tile = (int)atomicAdd(&g_qctr, 1u);
        __syncthreads();
        const int item = s_tile;
        if (item >= NITEMS) break;

        // -------- decode --------
        int op, p = 0, s = 0;
        if (item < XITEMS) { op = OPX; s = item; }
        else if (item < APHASE) { op = OPW1; p = (item - XITEMS) >> 7; s = (item - XITEMS) & 127; }
        else if (item < BPHASE) {
            int r = item - APHASE;
            int sp = r / SEGSZ;
            int ss = r % SEGSZ;
            if (ss < 128)       { op = OPG1; p = sp; s = ss; }
            else if (ss < 256)  { op = OPW1; p = sp + 2; s = ss - 128;
                                  if (p >= P_) continue; }
            else                { op = OPG2; p = sp - 2; s = ss - 256;
                                  if (p < 0) continue; }
        } else {
            int r = item - BPHASE;
            op = OPG2; p = 22 + (r >> 6); s = r & 63;
        }

        // ------------------------------------------------------------------
        // x convert chunk
        // ------------------------------------------------------------------
        if (op == OPX) {
            size_t base = (size_t)s * XF4 + tid;
            const float4* src = (const float4*)x;
            __half2* dst = (__half2*)xh;
#pragma unroll 8
            for (int i = 0; i < XF4 / 128; i++) {
                size_t idx = base + (size_t)i * 128;
                float4 v = __ldg(&src[idx]);
                dst[2 * idx]     = __floats2half2_rn(v.x, v.y);
                dst[2 * idx + 1] = __floats2half2_rn(v.z, v.w);
            }
            __threadfence(); __syncthreads();
            if (tid == 0) atomicAdd(&g_cnt_x, 1u);
            continue;
        }

        // ------------------------------------------------------------------
        // W1[p] convert chunk
        // ------------------------------------------------------------------
        if (op == OPW1) {
            size_t base = (size_t)p * (128 * (size_t)W1F4) + (size_t)s * W1F4 + tid;
            const float4* src = (const float4*)W1;
            __half2* dst = (__half2*)w1h;
#pragma unroll 8
            for (int i = 0; i < W1F4 / 128; i++) {
                size_t idx = base + (size_t)i * 128;
                float4 v = __ldg(&src[idx]);
                dst[2 * idx]     = __floats2half2_rn(v.x, v.y);
                dst[2 * idx + 1] = __floats2half2_rn(v.z, v.w);
            }
            __threadfence(); __syncthreads();
            if (tid == 0) atomicAdd(&g_cnt_w1[p], 1u);
            continue;
        }

        // ------------------------------------------------------------------
        // GEMM1 tile (p, bm, bn) + W2 cvt side job
        // ------------------------------------------------------------------
        if (op == OPG1) {
            const int tl = s;
            const int bn = tl & 15, bm = tl >> 4;
            if (tid == 0) {
                while (ld_acq(&g_cnt_x) < XITEMS) __nanosleep(64);
                while (ld_acq(&g_cnt_w1[p]) < 128) __nanosleep(64);
            }
            __syncthreads();

            float acc[4][8][4];
#pragma unroll
            for (int mf = 0; mf < 4; mf++)
#pragma unroll
                for (int nf = 0; nf < 8; nf++)
#pragma unroll
                    for (int i = 0; i < 4; i++) acc[mf][nf][i] = 0.f;

            const __half* Wp = w1h + (size_t)p * K1_ * N1_ + (size_t)bn * BN;

            auto load_A = [&](int kt, int buf) {
                uint32_t sbase = smem_u + buf * STGB;
#pragma unroll
                for (int i = 0; i < 8; i++) {
                    int c  = tid + i * 128;
                    int m  = c >> 3;
                    int kl = (c & 7) * 8;
                    int kg = kt * BK + kl;
                    int half_ = (kg >= H_) ? 1 : 0;
                    int pp    = p + half_;
                    int kk    = kg - half_ * H_;
                    int sz = 16;
                    if (pp >= P_) { pp = P_ - 1; sz = 0; }
                    const __half* ga = xh + ((size_t)(bm * BM + m) * P_ + pp) * H_ + kk;
                    cp_async16(sbase + (m * ASTRH + kl) * 2, ga, sz);
                }
            };
            auto load_B = [&](int kt, int buf) {
                uint32_t sbase = smem_u + buf * STGB;
#pragma unroll
                for (int i = 0; i < 8; i++) {
                    int c  = tid + i * 128;
                    int kb = c >> 4;
                    int nb = (c & 15) * 8;
                    const __half* gb = Wp + (size_t)(kt * BK + kb) * N1_ + nb;
                    cp_async16(sbase + ASZB + (kb * BSTRH + nb) * 2, gb, 16);
                }
            };

            uint32_t a[2][4][4], b[2][4][4];
            auto prefetch = [&](uint32_t sbase, int ks, int buf) {
                const uint32_t akk = sbase + aoff + ks * 32;
                const uint32_t bkk = sbase + boff + ks * (16 * BSTRH * 2);
#pragma unroll
                for (int f = 0; f < 4; f++) ldsm4(akk + f * (16 * ASTRH * 2), a[buf][f]);
#pragma unroll
                for (int nf = 0; nf < 4; nf++) ldsm4t(bkk + nf * 32, b[buf][nf]);
            };
            auto mma_block = [&](int buf) {
#pragma unroll
                for (int mf = 0; mf < 4; mf++)
#pragma unroll
                    for (int nf = 0; nf < 4; nf++) {
                        mma_f16_f32(acc[mf][2 * nf],     a[buf][mf], &b[buf][nf][0]);
                        mma_f16_f32(acc[mf][2 * nf + 1], a[buf][mf], &b[buf][nf][2]);
                    }
            };

            const int NKT = (p == P_ - 1) ? (H_ / BK) : (K1_ / BK);

            load_A(0, 0); load_B(0, 0); cp_commit();
            load_A(1, 1); load_B(1, 1); cp_commit();
            cp_wait<1>(); __syncthreads();
            prefetch(smem_u, 0, 0);

            for (int kt = 0; kt < NKT; ++kt) {
                const uint32_t sbase = smem_u + (kt % NSTG) * STGB;
                const bool more = (kt + 2 < NKT);
                const int  nbuf = (kt + 2) % NSTG;

                prefetch(sbase, 1, 1);
                if (more) load_A(kt + 2, nbuf);
                mma_block(0);
                prefetch(sbase, 2, 0);
                if (more) load_B(kt + 2, nbuf);
                mma_block(1);
                prefetch(sbase, 3, 1);
                mma_block(0);

                if (more) { cp_commit(); cp_wait<1>(); }
                else      { cp_wait<0>(); }
                __syncthreads();
                if (kt + 1 < NKT) prefetch(smem_u + ((kt + 1) % NSTG) * STGB, 0, 0);
                mma_block(1);
            }

            const float* brow = b1 + (size_t)p * N1_;
#pragma unroll
            for (int mf = 0; mf < 4; mf++) {
                int row0 = bm * BM + warpM * 64 + mf * 16 + g;
                size_t base0 = ((size_t)p * B_ + row0) * (size_t)N1_;
                size_t base8 = base0 + (size_t)8 * N1_;
#pragma unroll
                for (int nf = 0; nf < 8; nf++) {
                    int n = bn * BN + warpN * 64 + nf * 8 + cc * 2;
                    float bv0 = __ldg(brow + n);
                    float bv1 = __ldg(brow + n + 1);
                    float v0 = gelu_exact(acc[mf][nf][0] + bv0);
                    float v1 = gelu_exact(acc[mf][nf][1] + bv1);
                    float v2 = gelu_exact(acc[mf][nf][2] + bv0);
                    float v3 = gelu_exact(acc[mf][nf][3] + bv1);
                    *(__half2*)(h1h + base0 + n) = __floats2half2_rn(v0, v1);
                    *(__half2*)(h1h + base8 + n) = __floats2half2_rn(v2, v3);
                }
            }
            // Side job: convert W2 slice (tile id p*128+tl covers all of W2)
            {
                size_t base = ((size_t)p * 128 + tl) * 4096 + tid;
                const float4* w2src = (const float4*)W2;
                __half2* w2dst = (__half2*)w2h;
#pragma unroll 4
                for (int i = 0; i < 32; i++) {
                    size_t idx = base + (size_t)i * 128;
                    float4 v = __ldg(&w2src[idx]);
                    w2dst[2 * idx]     = __floats2half2_rn(v.x, v.y);
                    w2dst[2 * idx + 1] = __floats2half2_rn(v.z, v.w);
                }
            }
            __threadfence(); __syncthreads();
            if (tid == 0) atomicAdd(&g_cnt_g1[p], 1u);
            continue;
        }

        // ------------------------------------------------------------------
        // GEMM2 tile (p, bm, bn): fused L3 partials
        // ------------------------------------------------------------------
        {
            const int tl = s;
            const int bn = tl & 7, bm = tl >> 3;
            if (tid == 0) {
                while (ld_acq(&g_cnt_g1[p]) < 128) __nanosleep(64);
            }
            __syncthreads();

            {
                const float4* w3g = (const float4*)(W3 + ((size_t)p * N2_ + bn * BN) * OUTP);
                ((float4*)(smem_c + W3_OFF))[tid] = __ldg(&w3g[tid]);
            }

            float acc[4][8][4];
#pragma unroll
            for (int mf = 0; mf < 4; mf++)
#pragma unroll
                for (int nf = 0; nf < 8; nf++)
#pragma unroll
                    for (int i = 0; i < 4; i++) acc[mf][nf][i] = 0.f;

            const __half* Wp = w2h + (size_t)p * K2_ * N2_ + (size_t)bn * BN;

            auto load_A = [&](int kt, int buf) {
                uint32_t sbase = smem_u + buf * STGB;
#pragma unroll
                for (int i = 0; i < 8; i++) {
                    int c  = tid + i * 128;
                    int m  = c >> 3;
                    int kl = (c & 7) * 8;
                    const __half* ga = h1h + ((size_t)p * B_ + bm * BM + m) * (size_t)K2_
                                     + kt * BK + kl;
                    cp_async16(sbase + (m * ASTRH + kl) * 2, ga, 16);
                }
            };
            auto load_B = [&](int kt, int buf) {
                uint32_t sbase = smem_u + buf * STGB;
#pragma unroll
                for (int i = 0; i < 8; i++) {
                    int c  = tid + i * 128;
                    int kb = c >> 4;
                    int nb = (c & 15) * 8;
                    const __half* gb = Wp + (size_t)(kt * BK + kb) * N2_ + nb;
                    cp_async16(sbase + ASZB + (kb * BSTRH + nb) * 2, gb, 16);
                }
            };

            uint32_t a[2][4][4], b[2][4][4];
            auto prefetch = [&](uint32_t sbase, int ks, int buf) {
                const uint32_t akk = sbase + aoff + ks * 32;
                const uint32_t bkk = sbase + boff + ks * (16 * BSTRH * 2);
#pragma unroll
                for (int f = 0; f < 4; f++) ldsm4(akk + f * (16 * ASTRH * 2), a[buf][f]);
#pragma unroll
                for (int nf = 0; nf < 4; nf++) ldsm4t(bkk + nf * 32, b[buf][nf]);
            };
            auto mma_block = [&](int buf) {
#pragma unroll
                for (int mf = 0; mf < 4; mf++)
#pragma unroll
                    for (int nf = 0; nf < 4; nf++) {
                        mma_f16_f32(acc[mf][2 * nf],     a[buf][mf], &b[buf][nf][0]);
                        mma_f16_f32(acc[mf][2 * nf + 1], a[buf][mf], &b[buf][nf][2]);
                    }
            };

            const int NKT = K2_ / BK;

            load_A(0, 0); load_B(0, 0); cp_commit();
            load_A(1, 1); load_B(1, 1); cp_commit();
            cp_wait<1>(); __syncthreads();
            prefetch(smem_u, 0, 0);

            for (int kt = 0; kt < NKT; ++kt) {
                const uint32_t sbase = smem_u + (kt % NSTG) * STGB;
                const bool more = (kt + 2 < NKT);
                const int  nbuf = (kt + 2) % NSTG;

                prefetch(sbase, 1, 1);
                if (more) load_A(kt + 2, nbuf);
                mma_block(0);
                prefetch(sbase, 2, 0);
                if (more) load_B(kt + 2, nbuf);
                mma_block(1);
                prefetch(sbase, 3, 1);
                mma_block(0);

                if (more) { cp_commit(); cp_wait<1>(); }
                else      { cp_wait<0>(); }
                __syncthreads();
                if (kt + 1 < NKT) prefetch(smem_u + ((kt + 1) % NSTG) * STGB, 0, 0);
                mma_block(1);
            }

            const float* brow = b2 + (size_t)p * N2_;
            const float4* w3s = (const float4*)(smem_c + W3_OFF);
            float* sred = (float*)(smem_c + SRED_OFF);
            float pr[8][4];
#pragma unroll
            for (int rr = 0; rr < 8; rr++)
#pragma unroll
                for (int o = 0; o < 4; o++) pr[rr][o] = 0.f;

#pragma unroll
            for (int mf = 0; mf < 4; mf++) {
#pragma unroll
                for (int nf = 0; nf < 8; nf++) {
                    int ncol = warpN * 64 + nf * 8 + cc * 2;
                    float bv0 = __ldg(brow + bn * BN + ncol);
                    float bv1 = __ldg(brow + bn * BN + ncol + 1);
                    float v0 = gelu_exact(acc[mf][nf][0] + bv0);
                    float v1 = gelu_exact(acc[mf][nf][1] + bv1);
                    float v2 = gelu_exact(acc[mf][nf][2] + bv0);
                    float v3 = gelu_exact(acc[mf][nf][3] + bv1);
                    float4 wA = w3s[ncol];
                    float4 wB = w3s[ncol + 1];
                    int r0 = mf * 2, r1 = mf * 2 + 1;
                    pr[r0][0] += v0 * wA.x + v1 * wB.x;
                    pr[r0][1] += v0 * wA.y + v1 * wB.y;
                    pr[r0][2] += v0 * wA.z + v1 * wB.z;
                    pr[r0][3] += v0 * wA.w + v1 * wB.w;
                    pr[r1][0] += v2 * wA.x + v3 * wB.x;
                    pr[r1][1] += v2 * wA.y + v3 * wB.y;
                    pr[r1][2] += v2 * wA.z + v3 * wB.z;
                    pr[r1][3] += v2 * wA.w + v3 * wB.w;
                }
            }
#pragma unroll
            for (int rr = 0; rr < 8; rr++)
#pragma unroll
                for (int o = 0; o < 4; o++) {
                    float v = pr[rr][o];
                    v += __shfl_xor_sync(0xffffffffu, v, 1);
                    v += __shfl_xor_sync(0xffffffffu, v, 2);
                    pr[rr][o] = v;
                }
            if (cc == 0) {
#pragma unroll
                for (int rr = 0; rr < 8; rr++) {
                    int row = warpM * 64 + (rr >> 1) * 16 + (rr & 1) * 8 + g;
#pragma unroll
                    for (int o = 0; o < 4; o++)
                        sred[row * 8 + o * 2 + warpN] = pr[rr][o];
                }
            }
            __syncthreads();
            {
                int row = tid;
                size_t base = (((size_t)p * B_ + bm * BM + row) * 8 + bn) * OUTP;
#pragma unroll
                for (int o = 0; o < 4; o++)
                    part[base + o] = sred[row * 8 + o * 2] + sred[row * 8 + o * 2 + 1];
            }
            __syncthreads();
        }
    }
}

// ---------------------------------------------------------------------------
// L3 finisher: out[b, p*4+o] = relu(b3[p][o] + sum_{q=0..7} part[p][b][q][o])
// ---------------------------------------------------------------------------
__global__ void l3f_kernel(const float* __restrict__ part, const float* __restrict__ b3,
                           float* __restrict__ out) {
    int idx = blockIdx.x * blockDim.x + threadIdx.x;
    if (idx >= B_ * P_ * OUTP) return;
    int b = idx / (P_ * OUTP);
    int q = idx % (P_ * OUTP);
    int p = q / OUTP;
    int o = q % OUTP;
    const float* pp = part + (((size_t)p * B_ + b) * 8) * OUTP + o;
    float s = b3[p * OUTP + o];
#pragma unroll
    for (int j = 0; j < 8; j++) s += pp[j * OUTP];
    out[idx] = fmaxf(s, 0.f);
}

// ---------------------------------------------------------------------------
extern "C" void kernel_launch(void* const* d_in, const int* in_sizes, int n_in,
                              void* d_out, int out_size) {
    const float* x  = (const float*)d_in[0];
    const float* W1 = (const float*)d_in[1];
    const float* b1 = (const float*)d_in[2];
    const float* W2 = (const float*)d_in[3];
    const float* b2 = (const float*)d_in[4];
    const float* W3 = (const float*)d_in[5];
    const float* b3 = (const float*)d_in[6];
    float* out = (float*)d_out;

    __half *xh, *w1h, *w2h, *h1h;
    float *part;
    cudaGetSymbolAddress((void**)&xh,  g_xh);
    cudaGetSymbolAddress((void**)&w1h, g_w1h);
    cudaGetSymbolAddress((void**)&w2h, g_w2h);
    cudaGetSymbolAddress((void**)&h1h, g_h1h);
    cudaGetSymbolAddress((void**)&part, g_part);

    int smCount = 148;
    cudaDeviceGetAttribute(&smCount, cudaDevAttrMultiProcessorCount, 0);
    const int nCTA = 2 * smCount;

    cudaFuncSetAttribute((const void*)mega_kernel,
                         cudaFuncAttributeMaxDynamicSharedMemorySize, SMEM_ALL);

    // Reset counters (must be first each replay)
    reset_kernel<<<1, 1>>>();
    // Fused pipeline with dependency lookahead
    mega_kernel<<<nCTA, 128, SMEM_ALL>>>(x, W1, b1, W2, b2, W3,
                                         xh, w1h, w2h, h1h, part);
    // L3 finisher
    l3f_kernel<<<(B_ * P_ * OUTP + 255) / 256, 256>>>(part, b3, out);
}